// round 1
// baseline (speedup 1.0000x reference)
#include <cuda_runtime.h>
#include <math.h>

// Shapes
#define Bsz 8
#define Cch 32
#define Hh  256
#define Ww  256
#define IMG 256   // Bsz*Cch
#define NK1 64    // rows kept: k1 in [0,32) U [224,256)
#define NK2 32    // cols kept: k2 in [0,32)
#define KK  64    // 2*NK2 (interleaved re/im)

// Scratch (static device globals; no allocations allowed)
__device__ float gZ [IMG*Hh*KK];     // F1 out: [img][h][2*k2]
__device__ float gY [IMG*NK1*KK];    // F2 out: [img][k1i][2*k2]
__device__ float gF [IMG*NK1*KK];    // mix out
__device__ float gT [IMG*KK*Hh];     // I1 out: [img][kk][h]  (transposed for coalesced I2)
__device__ float gW1[Ww*KK];         // F1 weights [w][2*k2]
__device__ float gE2[Hh*NK1*2];      // F2 weights [h][k1i] complex, /256
__device__ float gEI[NK1*Hh*2];      // I1 weights [k1i][h] complex, /16
__device__ float gWB[KK*Ww];         // I2 weights [kk][w]
__device__ float gKCP[2*32*32*32*2]; // kernel^r
__device__ float gG  [2*32*32*32*2]; // circulant taps [s][d][m1][m2] complex

// ---------------- weight tables ----------------
__global__ void k_tables() {
    int tid = blockIdx.x * 256 + threadIdx.x;  // 0..16383
    const float W0 = 6.2831853071795864769f / 256.0f;
    if (tid < 8192) {  // W1: 256 w x 32 k2
        int w = tid >> 5, k2 = tid & 31;
        int a = (k2 * w) & 255;
        float s, c; sincosf(a * W0, &s, &c);
        gW1[w * KK + 2 * k2]     = c;
        gW1[w * KK + 2 * k2 + 1] = -s;
    }
    {   // E2 / EI: 256 h x 64 k1i
        int h = tid >> 6, k1i = tid & 63;
        int k1 = (k1i < 32) ? k1i : (192 + k1i);
        int a = (k1 * h) & 255;
        float s, c; sincosf(a * W0, &s, &c);
        gE2[(h * NK1 + k1i) * 2]     =  c * (1.0f / 256.0f);
        gE2[(h * NK1 + k1i) * 2 + 1] = -s * (1.0f / 256.0f);
        gEI[(k1i * Hh + h) * 2]      =  c * (1.0f / 16.0f);
        gEI[(k1i * Hh + h) * 2 + 1]  =  s * (1.0f / 16.0f);
    }
    {   // WB: 64 kk x 256 w
        int kk = tid >> 8, w = tid & 255;
        int k2 = kk >> 1;
        int a = (k2 * w) & 255;
        float s, c; sincosf(a * W0, &s, &c);
        float v;
        if ((kk & 1) == 0) v = (k2 == 0 ? 1.0f : 2.0f) * (1.0f / 16.0f) * c;
        else               v = (k2 == 0 ? 0.0f : -(2.0f / 16.0f) * s);
        gWB[kk * Ww + w] = v;
    }
}

// ---------------- kernel^r (elementwise complex pow) ----------------
__global__ void k_pow(const float* __restrict__ kern, const float* __restrict__ rp) {
    int idx = blockIdx.x * 256 + threadIdx.x;  // 65536
    float kr = kern[2 * idx], ki = kern[2 * idx + 1];
    float r = *rp;
    float outr, outi;
    if (r == 1.0f) { outr = kr; outi = ki; }
    else {
        float m2 = kr * kr + ki * ki;
        if (m2 == 0.0f) { outr = 0.0f; outi = 0.0f; }
        else {
            float mag = expf(0.5f * r * logf(m2));
            float th = atan2f(ki, kr) * r;
            float s, c; sincosf(th, &s, &c);
            outr = mag * c; outi = mag * s;
        }
    }
    gKCP[2 * idx] = outr; gKCP[2 * idx + 1] = outi;
}

// ---------------- circulant taps G = (1/32) * ifft_j(kcp) ----------------
__global__ void k_g() {
    __shared__ float tw[64];
    int tid = threadIdx.x;  // 256
    if (tid < 32) {
        float s, c; sincosf(tid * (6.2831853071795864769f / 32.0f), &s, &c);
        tw[2 * tid] = c; tw[2 * tid + 1] = s;
    }
    __syncthreads();
    int bi = blockIdx.x;           // 256
    int s_ = bi >> 7;
    int rest = bi & 127;
    int m1 = rest >> 2, dq = rest & 3;
    int d = dq * 8 + (tid >> 5);
    int m2 = tid & 31;
    float ar = 0.0f, ai = 0.0f;
    #pragma unroll 8
    for (int j = 0; j < 32; j++) {
        int a = (j * d) & 31;
        float tr = tw[2 * a], ti = tw[2 * a + 1];
        int base = (((s_ * 32 + j) * 32 + m1) * 32 + m2) * 2;
        float cr = gKCP[base], ci = gKCP[base + 1];
        ar += tr * cr - ti * ci;
        ai += tr * ci + ti * cr;
    }
    int ob = (((s_ * 32 + d) * 32 + m1) * 32 + m2) * 2;
    gG[ob]     = ar * (1.0f / 32.0f);
    gG[ob + 1] = ai * (1.0f / 32.0f);
}

// ---------------- F1: Z[row][kk] = sum_w x[row][w] * W1[w][kk] ----------------
__global__ void k_f1(const float* __restrict__ x) {
    __shared__ float Xs[64][68];
    __shared__ float Ws[64][68];
    int tid = threadIdx.x;      // 128
    int r0 = blockIdx.x * 64;   // 1024 blocks
    int ty = tid >> 3;          // 0..15 -> 4 rows each
    int tx = tid & 7;           // 0..7  -> 8 cols each
    float acc[4][8];
    #pragma unroll
    for (int i = 0; i < 4; i++)
        #pragma unroll
        for (int j = 0; j < 8; j++) acc[i][j] = 0.0f;

    for (int kt = 0; kt < 4; kt++) {
        #pragma unroll
        for (int t = 0; t < 32; t++) {
            int lin = tid + t * 128;
            int row = lin >> 6, col = lin & 63;
            Xs[row][col] = x[(r0 + row) * 256 + kt * 64 + col];
            Ws[row][col] = gW1[(kt * 64 + row) * KK + col];
        }
        __syncthreads();
        #pragma unroll 4
        for (int k = 0; k < 64; k++) {
            float xa[4], wv[8];
            #pragma unroll
            for (int i = 0; i < 4; i++) xa[i] = Xs[ty * 4 + i][k];
            #pragma unroll
            for (int j = 0; j < 8; j++) wv[j] = Ws[k][tx * 8 + j];
            #pragma unroll
            for (int i = 0; i < 4; i++)
                #pragma unroll
                for (int j = 0; j < 8; j++) acc[i][j] += xa[i] * wv[j];
        }
        __syncthreads();
    }
    #pragma unroll
    for (int i = 0; i < 4; i++)
        #pragma unroll
        for (int j = 0; j < 8; j++)
            gZ[(r0 + ty * 4 + i) * KK + tx * 8 + j] = acc[i][j];
}

// ---------------- F2: Y[img][k1i][k2] = sum_h E2[h][k1i] * Z[img][h][k2] ----------------
__global__ void k_f2() {
    __shared__ float Zs[128][64];
    int tid = threadIdx.x;      // 256
    int img = blockIdx.x;       // 256
    int k1i = tid >> 2;
    int g = tid & 3;            // 8 k2 each
    float accr[8], acci[8];
    #pragma unroll
    for (int q = 0; q < 8; q++) { accr[q] = 0.0f; acci[q] = 0.0f; }
    const float* Zimg = gZ + img * Hh * KK;
    for (int half = 0; half < 2; half++) {
        __syncthreads();
        #pragma unroll
        for (int t = 0; t < 32; t++) {
            int lin = tid + t * 256;
            int row = lin >> 6, col = lin & 63;
            Zs[row][col] = Zimg[(half * 128 + row) * KK + col];
        }
        __syncthreads();
        for (int hh = 0; hh < 128; hh++) {
            int h = half * 128 + hh;
            float2 e = *(const float2*)&gE2[(h * NK1 + k1i) * 2];
            const float* zrow = &Zs[hh][g * 16];
            float4 z0 = *(const float4*)&zrow[0];
            float4 z1 = *(const float4*)&zrow[4];
            float4 z2 = *(const float4*)&zrow[8];
            float4 z3 = *(const float4*)&zrow[12];
            float zr[8] = {z0.x, z0.z, z1.x, z1.z, z2.x, z2.z, z3.x, z3.z};
            float zi[8] = {z0.y, z0.w, z1.y, z1.w, z2.y, z2.w, z3.y, z3.w};
            #pragma unroll
            for (int q = 0; q < 8; q++) {
                accr[q] += e.x * zr[q] - e.y * zi[q];
                acci[q] += e.x * zi[q] + e.y * zr[q];
            }
        }
    }
    float* out = gY + (img * NK1 + k1i) * KK + g * 16;
    #pragma unroll
    for (int q = 0; q < 8; q++) { out[2 * q] = accr[q]; out[2 * q + 1] = acci[q]; }
}

// ---------------- Mix: F[b][o][k1i][k2] = sum_c G[s][(o-c)%32][m1][k2] * Y[b][c][k1i][k2] ----------------
__global__ void k_mix() {
    __shared__ float Ys[8][32][16];        // [b][c][2*kq]
    __shared__ float Gr[32][9], Gi[32][9]; // padded
    int tid = threadIdx.x;   // 256
    int bi = blockIdx.x;     // 256: (k1i, k2-quad)
    int k1i = bi >> 2, q = bi & 3;
    int s_ = (k1i < 32) ? 0 : 1;
    int m1 = k1i & 31;
    int b = tid >> 5, c = tid & 31;
    {
        const float4* ysrc = (const float4*)(gY + ((b * 32 + c) * NK1 + k1i) * KK + q * 16);
        float4* dst = (float4*)&Ys[b][c][0];
        #pragma unroll
        for (int t = 0; t < 4; t++) dst[t] = ysrc[t];
    }
    {
        int d = tid >> 3, kq = tid & 7;
        int m2 = q * 8 + kq;
        int gi = (((s_ * 32 + d) * 32 + m1) * 32 + m2) * 2;
        Gr[d][kq] = gG[gi]; Gi[d][kq] = gG[gi + 1];
    }
    __syncthreads();
    int o = c;
    float ar[8] = {0, 0, 0, 0, 0, 0, 0, 0}, ai[8] = {0, 0, 0, 0, 0, 0, 0, 0};
    for (int cc = 0; cc < 32; cc++) {
        int d = (o - cc) & 31;
        #pragma unroll
        for (int kq = 0; kq < 8; kq++) {
            float gr = Gr[d][kq], gim = Gi[d][kq];
            float yr = Ys[b][cc][2 * kq], yi = Ys[b][cc][2 * kq + 1];
            ar[kq] += gr * yr - gim * yi;
            ai[kq] += gr * yi + gim * yr;
        }
    }
    float* fo = gF + ((b * 32 + o) * NK1 + k1i) * KK + q * 16;
    #pragma unroll
    for (int kq = 0; kq < 8; kq++) { fo[2 * kq] = ar[kq]; fo[2 * kq + 1] = ai[kq]; }
}

// ---------------- I1: T[img][kk][h] = sum_k1 EI[k1i][h] * F[img][k1i][k2] ----------------
__global__ void k_i1() {
    __shared__ float Fs[NK1][KK];  // 16KB
    int tid = threadIdx.x;  // 256 = h
    int img = blockIdx.x;   // 256
    const float* fimg = gF + img * NK1 * KK;
    #pragma unroll
    for (int t = 0; t < 16; t++) {
        int lin = tid + t * 256;
        ((float*)Fs)[lin] = fimg[lin];
    }
    __syncthreads();
    float tr[32], ti[32];
    #pragma unroll
    for (int k2 = 0; k2 < 32; k2++) { tr[k2] = 0.0f; ti[k2] = 0.0f; }
    int h = tid;
    for (int k1i = 0; k1i < 64; k1i++) {
        float2 e = *(const float2*)&gEI[(k1i * Hh + h) * 2];
        #pragma unroll
        for (int k2 = 0; k2 < 32; k2++) {
            float fr = Fs[k1i][2 * k2], fi = Fs[k1i][2 * k2 + 1];
            tr[k2] += e.x * fr - e.y * fi;
            ti[k2] += e.x * fi + e.y * fr;
        }
    }
    float* tout = gT + img * KK * Hh;
    #pragma unroll
    for (int k2 = 0; k2 < 32; k2++) {
        tout[(2 * k2) * Hh + h]     = tr[k2];
        tout[(2 * k2 + 1) * Hh + h] = ti[k2];
    }
}

// ---------------- I2: y[img][h][w] = sum_kk T[img][kk][h] * WB[kk][w] ----------------
__global__ void k_i2(float* __restrict__ out) {
    __shared__ float Ts[64][68];
    __shared__ float Wb[64][68];
    int tid = threadIdx.x;  // 128
    int bi = blockIdx.x;    // 256*4*4 = 4096
    int img = bi >> 4;
    int hb = (bi >> 2) & 3;
    int wb = bi & 3;
    int h0 = hb * 64, w0 = wb * 64;
    #pragma unroll
    for (int t = 0; t < 32; t++) {
        int lin = tid + t * 128;
        int row = lin >> 6, col = lin & 63;
        Ts[row][col] = gT[(img * KK + row) * Hh + h0 + col];
        Wb[row][col] = gWB[row * Ww + w0 + col];
    }
    __syncthreads();
    int ty = tid >> 3, tx = tid & 7;
    float acc[4][8];
    #pragma unroll
    for (int i = 0; i < 4; i++)
        #pragma unroll
        for (int j = 0; j < 8; j++) acc[i][j] = 0.0f;
    #pragma unroll 4
    for (int k = 0; k < 64; k++) {
        float ta[4], wv[8];
        #pragma unroll
        for (int i = 0; i < 4; i++) ta[i] = Ts[k][ty * 4 + i];
        #pragma unroll
        for (int j = 0; j < 8; j++) wv[j] = Wb[k][tx * 8 + j];
        #pragma unroll
        for (int i = 0; i < 4; i++)
            #pragma unroll
            for (int j = 0; j < 8; j++) acc[i][j] += ta[i] * wv[j];
    }
    #pragma unroll
    for (int i = 0; i < 4; i++)
        #pragma unroll
        for (int j = 0; j < 8; j++)
            out[(img * Hh + h0 + ty * 4 + i) * Ww + w0 + tx * 8 + j] = acc[i][j];
}

extern "C" void kernel_launch(void* const* d_in, const int* in_sizes, int n_in,
                              void* d_out, int out_size) {
    const float* x    = (const float*)d_in[0];
    const float* kern = (const float*)d_in[1];
    const float* r    = (const float*)d_in[2];
    float* out = (float*)d_out;

    k_tables<<<64, 256>>>();
    k_pow<<<256, 256>>>(kern, r);
    k_g<<<256, 256>>>();
    k_f1<<<1024, 128>>>(x);
    k_f2<<<256, 256>>>();
    k_mix<<<256, 256>>>();
    k_i1<<<256, 256>>>();
    k_i2<<<4096, 128>>>(out);
}